// round 7
// baseline (speedup 1.0000x reference)
#include <cuda_runtime.h>
#include <cstdint>

#define TH 1.0f
#define EPS_BN 1e-5f

// scratch (no allocations allowed -> device globals)
__device__ __align__(1024) float g_dm[256 * 256];
__device__ int g_rowok[256];
__device__ int g_done = 0;     // reset by last block each run (replay-safe)

__device__ __forceinline__ uint32_t smem_u32(const void* p) {
    uint32_t a;
    asm("{ .reg .u64 t; cvta.to.shared.u64 t, %1; cvt.u32.u64 %0, t; }"
        : "=r"(a) : "l"(p));
    return a;
}

// ---------------------------------------------------------------------------
// K1: 256 blocks x 256 thr. Block n computes dm row n into g_dm + rowok[n].
// Last block (done counter) computes group_indices:
//   FAST PATH: if every row r>=1 has an ok edge to some c<r, the ordered scan
//   collapses everything into the component labeled 0 -> all ranks 0.
//   SLOW PATH: exact row-parallel replica of the reference lax.scan.
// ---------------------------------------------------------------------------
__global__ void dm_kernel(const float* __restrict__ v,
                          const float* __restrict__ w1,
                          const float* __restrict__ b1,
                          const float* __restrict__ bn_gamma,
                          const float* __restrict__ bn_beta,
                          const float* __restrict__ bn_mean,
                          const float* __restrict__ bn_var,
                          const float* __restrict__ w2,
                          const float* __restrict__ b2,
                          float* __restrict__ out_gi) {
    __shared__ float sa[32], sw0[32], sw1[32], sb[32];
    __shared__ float sK;
    __shared__ int s_islast;
    int tid = threadIdx.x;
    if (tid < 32) {
        float scale = bn_gamma[tid] * rsqrtf(bn_var[tid] + EPS_BN);
        float w2o = w2[tid];
        sa[tid]  = w2o * scale;
        sw0[tid] = w1[tid * 2 + 0];
        sw1[tid] = w1[tid * 2 + 1];
        sb[tid]  = b1[tid];
        float kpart = w2o * (bn_beta[tid] - bn_mean[tid] * scale);
        #pragma unroll
        for (int off = 16; off > 0; off >>= 1)
            kpart += __shfl_down_sync(0xffffffffu, kpart, off);
        if (tid == 0) sK = kpart + b2[0];
    }
    __syncthreads();

    int n = blockIdx.x;
    int m = tid;
    const int base = 127 * 256;            // v_rel[0, c, 127, :]
    float d0 = v[base + n] - v[base + m];
    float d1 = v[32768 + base + n] - v[32768 + base + m];

    float sp = sK, sn = sK;
    #pragma unroll
    for (int o = 0; o < 32; o++) {
        float lin = sw0[o] * d0 + sw1[o] * d1;
        sp += sa[o] * fmaxf(lin + sb[o], 0.0f);
        sn += sa[o] * fmaxf(sb[o] - lin, 0.0f);
    }
    float val = 0.5f * (expf(sp) + expf(sn));
    g_dm[n * 256 + m] = val;

    int anyok = __syncthreads_or((m < n) && (val <= TH));
    if (tid == 0) {
        g_rowok[n] = anyok;
        __threadfence();
        int old = atomicAdd(&g_done, 1);
        s_islast = (old == 255);
    }
    __syncthreads();
    if (!s_islast) return;
    __threadfence();

    int rowok = g_rowok[tid];
    bool fast = __syncthreads_and(tid == 0 || rowok);
    if (fast) {
        out_gi[tid] = 0.0f;
    } else {
        __shared__ int comp[256];
        __shared__ int firstidx[256];
        __shared__ int marked[256];
        __shared__ int cstar;
        __shared__ int newcomp;
        comp[tid] = tid;
        __syncthreads();
        for (int r = 1; r < 256; r++) {
            firstidx[tid] = 0x7fffffff;
            marked[tid] = 0;
            if (tid == 0) cstar = -1;
            __syncthreads();
            int myc = comp[tid];
            int rcomp = comp[r];
            bool okc = (tid < r) && (g_dm[r * 256 + tid] <= TH);
            if (okc) { atomicMin(&firstidx[myc], tid); marked[myc] = 1; }
            if (tid == r) marked[myc] = 1;
            __syncthreads();
            if (okc && myc != rcomp && firstidx[myc] == tid)
                atomicMax(&cstar, tid);
            __syncthreads();
            int cs = cstar;
            if (cs >= 0 && tid == cs) newcomp = myc;
            __syncthreads();
            if (cs >= 0 && marked[myc]) comp[tid] = newcomp;
            __syncthreads();
        }
        __shared__ int pres[256];
        pres[tid] = 0;
        __syncthreads();
        pres[comp[tid]] = 1;
        __syncthreads();
        for (int off = 1; off < 256; off <<= 1) {
            int t = (tid >= off) ? pres[tid - off] : 0;
            __syncthreads();
            pres[tid] += t;
            __syncthreads();
        }
        out_gi[tid] = (float)(pres[comp[tid]] - 1);
    }
    __syncthreads();
    if (tid == 0) g_done = 0;
}

// ---------------------------------------------------------------------------
// K2: pure TMA bulk streaming, 2048 blocks x 128 thr, 32KB smem staging.
//  blocks 0..1023   : out[b*8192 .. +8192) = v[b*8192 .. +8192)   (v_grouped)
//  blocks 1024..2047: i=b-1024, t=i>>3, p=i&7:
//       dist_full copy t, chunk p: out_dist + t*65536 + p*8192 <- g_dm + p*8192
// Each block: one 32KB cp.async.bulk G2S + one 32KB cp.async.bulk S2G.
// ---------------------------------------------------------------------------
__global__ void __launch_bounds__(128) stream_kernel(const float* __restrict__ v,
                                                     float* __restrict__ out) {
    __shared__ __align__(1024) float buf[8192];
    __shared__ __align__(8) unsigned long long mbar;
    int b = blockIdx.x;
    int tid = threadIdx.x;

    const float* src;
    float* dst;
    if (b < 1024) {
        src = v + b * 8192;
        dst = out + b * 8192;
    } else {
        int i = b - 1024;
        int t = i >> 3;
        int p = i & 7;
        src = g_dm + p * 8192;
        dst = out + 8388864 + t * 65536 + p * 8192;
    }

    uint32_t sbuf = smem_u32(buf);
    uint32_t mb = smem_u32(&mbar);
    if (tid == 0) {
        asm volatile("mbarrier.init.shared.b64 [%0], %1;"
                     :: "r"(mb), "r"(1) : "memory");
    }
    __syncthreads();

    if (tid == 0) {
        asm volatile("mbarrier.arrive.expect_tx.shared.b64 _, [%0], %1;"
                     :: "r"(mb), "r"(32768u) : "memory");
        asm volatile(
            "cp.async.bulk.shared::cluster.global.mbarrier::complete_tx::bytes "
            "[%0], [%1], %2, [%3];"
            :: "r"(sbuf), "l"(src), "r"(32768u), "r"(mb) : "memory");

        uint32_t done = 0;
        while (!done) {
            asm volatile(
                "{\n\t.reg .pred p;\n\t"
                "mbarrier.try_wait.parity.shared.b64 p, [%1], %2;\n\t"
                "selp.u32 %0, 1, 0, p;\n\t}"
                : "=r"(done) : "r"(mb), "r"(0u) : "memory");
        }

        asm volatile(
            "cp.async.bulk.global.shared::cta.bulk_group [%0], [%1], %2;"
            :: "l"(dst), "r"(sbuf), "r"(32768u) : "memory");
        asm volatile("cp.async.bulk.commit_group;" ::: "memory");
        asm volatile("cp.async.bulk.wait_group 0;" ::: "memory");
    }
}

extern "C" void kernel_launch(void* const* d_in, const int* in_sizes, int n_in,
                              void* d_out, int out_size) {
    const float* v_rel    = (const float*)d_in[0];
    const float* w1       = (const float*)d_in[1];
    const float* b1       = (const float*)d_in[2];
    const float* bn_gamma = (const float*)d_in[3];
    const float* bn_beta  = (const float*)d_in[4];
    const float* bn_mean  = (const float*)d_in[5];
    const float* bn_var   = (const float*)d_in[6];
    const float* w2       = (const float*)d_in[7];
    const float* b2       = (const float*)d_in[8];
    float* out = (float*)d_out;

    dm_kernel<<<256, 256>>>(v_rel, w1, b1, bn_gamma, bn_beta, bn_mean,
                            bn_var, w2, b2, out + 8388608);
    stream_kernel<<<2048, 128>>>(v_rel, out);
}

// round 8
// speedup vs baseline: 1.2220x; 1.2220x over previous
#include <cuda_runtime.h>
#include <cstdint>

#define TH 1.0f
#define EPS_BN 1e-5f

// scratch (no allocations allowed -> device globals)
__device__ float g_dm[256 * 256];
__device__ int   g_rowok[256];
__device__ int   g_done = 0;   // reset to 0 by the last block each run (replay-safe)

// ---------------------------------------------------------------------------
// Single fused kernel, 2560 blocks x 256 threads:
//  blocks 0..511 : dm row n = b>>1, slice s = b&1. Compute the MLP row
//    (thread m -> dm[n][m]) into shared, write 64 t-copies into
//    dist_mat_full (t in [s*64, s*64+64)). Slice 0 stores g_dm row + rowok[n]
//    and joins a done-counter; the LAST slice-0 block computes group_indices
//    in-kernel (fast path all-zeros; exact lax.scan replica fallback).
//  blocks 512..2559 : float4 slab copy v_rel -> v_grouped
//    (stop_gradient(v - v_soft) + v_soft == v exactly).
// ---------------------------------------------------------------------------
__global__ void fused_kernel(const float* __restrict__ v,
                             const float* __restrict__ w1,
                             const float* __restrict__ b1,
                             const float* __restrict__ bn_gamma,
                             const float* __restrict__ bn_beta,
                             const float* __restrict__ bn_mean,
                             const float* __restrict__ bn_var,
                             const float* __restrict__ w2,
                             const float* __restrict__ b2,
                             float* __restrict__ out) {
    int b = blockIdx.x;
    int tid = threadIdx.x;

    if (b >= 512) {
        // ---- copy part: v_grouped = v_rel (2M float4 over 2048 blocks) ----
        const float4* __restrict__ v4 = (const float4*)v;
        float4* __restrict__ ov = (float4*)out;
        int i0 = (b - 512) * 1024 + tid;
        float4 r0 = v4[i0];
        float4 r1 = v4[i0 + 256];
        float4 r2 = v4[i0 + 512];
        float4 r3 = v4[i0 + 768];
        __stcs(&ov[i0],       r0);
        __stcs(&ov[i0 + 256], r1);
        __stcs(&ov[i0 + 512], r2);
        __stcs(&ov[i0 + 768], r3);
        return;
    }

    // ---- dm + dist broadcast part ----
    __shared__ __align__(16) float srow[256];
    __shared__ float sa[32], sw0[32], sw1[32], sb[32];
    __shared__ float sK;
    __shared__ int s_islast;
    if (tid < 32) {
        float scale = bn_gamma[tid] * rsqrtf(bn_var[tid] + EPS_BN);
        float w2o = w2[tid];
        sa[tid]  = w2o * scale;
        sw0[tid] = w1[tid * 2 + 0];
        sw1[tid] = w1[tid * 2 + 1];
        sb[tid]  = b1[tid];
        float kpart = w2o * (bn_beta[tid] - bn_mean[tid] * scale);
        #pragma unroll
        for (int off = 16; off > 0; off >>= 1)
            kpart += __shfl_down_sync(0xffffffffu, kpart, off);
        if (tid == 0) sK = kpart + b2[0];
    }
    __syncthreads();

    int n = b >> 1;
    int s = b & 1;
    int m = tid;
    // x[c][i] = v_rel[0, c, 127, i], layout (1,256,128,256)
    const int base = 127 * 256;
    float d0 = v[base + n] - v[base + m];
    float d1 = v[32768 + base + n] - v[32768 + base + m];

    float sp = sK, sn = sK;
    #pragma unroll
    for (int o = 0; o < 32; o++) {
        float lin = sw0[o] * d0 + sw1[o] * d1;
        sp += sa[o] * fmaxf(lin + sb[o], 0.0f);
        sn += sa[o] * fmaxf(sb[o] - lin, 0.0f);
    }
    float val = 0.5f * (expf(sp) + expf(sn));
    srow[m] = val;

    int anyok = __syncthreads_or((m < n) && (val <= TH));   // doubles as barrier
    if (s == 0) {
        g_dm[n * 256 + m] = val;
        if (tid == 0) g_rowok[n] = anyok;
    }

    // dist_mat_full broadcast: t-copies [s*64, s*64+64), float4 granularity.
    const float4* __restrict__ src = (const float4*)srow;
    float4* __restrict__ dst = (float4*)(out + 8388864);
    int tbase = s * 64;
    #pragma unroll
    for (int k = 0; k < 16; k++) {
        int idx = tid + k * 256;        // 0..4095
        int t = tbase + (idx >> 6);
        int q = idx & 63;
        __stcs(&dst[t * 16384 + n * 64 + q], src[q]);
    }

    if (s != 0) return;

    // ---- done-counter handshake: last slice-0 block computes groups ----
    if (tid == 0) {
        __threadfence();                       // commit g_dm row + rowok
        int old = atomicAdd(&g_done, 1);
        s_islast = (old == 255);
    }
    __syncthreads();
    if (!s_islast) return;
    __threadfence();                           // see all rows' writes

    float* __restrict__ out_gi = out + 8388608;
    int rowok = g_rowok[tid];
    bool fast = __syncthreads_and(tid == 0 || rowok);
    if (fast) {
        // every row r>=1 merges into the component labeled 0 -> all ranks 0
        out_gi[tid] = 0.0f;
    } else {
        // ---- exact fallback: row-parallel replica of reference lax.scan ----
        __shared__ int comp[256];
        __shared__ int firstidx[256];
        __shared__ int marked[256];
        __shared__ int cstar;
        __shared__ int newcomp;
        comp[tid] = tid;
        __syncthreads();

        for (int r = 1; r < 256; r++) {
            firstidx[tid] = 0x7fffffff;
            marked[tid] = 0;
            if (tid == 0) cstar = -1;
            __syncthreads();

            int myc = comp[tid];
            int rcomp = comp[r];
            bool okc = (tid < r) && (g_dm[r * 256 + tid] <= TH);
            if (okc) {
                atomicMin(&firstidx[myc], tid);
                marked[myc] = 1;
            }
            if (tid == r) marked[myc] = 1;
            __syncthreads();

            if (okc && myc != rcomp && firstidx[myc] == tid)
                atomicMax(&cstar, tid);
            __syncthreads();

            int cs = cstar;
            if (cs >= 0 && tid == cs) newcomp = myc;
            __syncthreads();
            if (cs >= 0 && marked[myc]) comp[tid] = newcomp;
            __syncthreads();
        }

        __shared__ int pres[256];
        pres[tid] = 0;
        __syncthreads();
        pres[comp[tid]] = 1;
        __syncthreads();
        for (int off = 1; off < 256; off <<= 1) {
            int t = (tid >= off) ? pres[tid - off] : 0;
            __syncthreads();
            pres[tid] += t;
            __syncthreads();
        }
        out_gi[tid] = (float)(pres[comp[tid]] - 1);
    }
    __syncthreads();
    if (tid == 0) g_done = 0;                  // reset for next graph replay
}

extern "C" void kernel_launch(void* const* d_in, const int* in_sizes, int n_in,
                              void* d_out, int out_size) {
    const float* v_rel    = (const float*)d_in[0];
    const float* w1       = (const float*)d_in[1];
    const float* b1       = (const float*)d_in[2];
    const float* bn_gamma = (const float*)d_in[3];
    const float* bn_beta  = (const float*)d_in[4];
    const float* bn_mean  = (const float*)d_in[5];
    const float* bn_var   = (const float*)d_in[6];
    const float* w2       = (const float*)d_in[7];
    const float* b2       = (const float*)d_in[8];
    float* out = (float*)d_out;

    fused_kernel<<<2560, 256>>>(v_rel, w1, b1, bn_gamma, bn_beta, bn_mean,
                                bn_var, w2, b2, out);
}